// round 2
// baseline (speedup 1.0000x reference)
#include <cuda_runtime.h>

// Problem constants (fixed shapes for this problem)
#define NNODE 10000
#define NEDGE 160000
#define NMUL  16

// Scratch (static device allocations — allowed; cudaMalloc is not)
__device__ __align__(16) float g_T[972];                 // T[a][b][d] padded to [81][12]
__device__ __align__(16) float g_w[(size_t)NEDGE * 48];  // MLP output w[e][48]

// ---------------------------------------------------------------------------
// ShiftedSoftPlus: softplus(x) - ln2, stable form max(x,0)+log1p(exp(-|x|))
// ---------------------------------------------------------------------------
__device__ __forceinline__ float sspf(float x) {
    float e = __expf(-fabsf(x));
    return fmaxf(x, 0.0f) + __logf(1.0f + e) - 0.69314718055994531f;
}

// ---------------------------------------------------------------------------
// kprep: build T[a][b][d] = sum_{s,t} Gx[a,s,t] * Gf[b,s,t] * P[s,t,d] / denom
//   Gx/Gf: real 9x9 grid of each spherical basis vector through
//          pad -> ifftshift -> truncate -> irfft2 (numpy Im(DC)-dropped conv.)
//   P:     rfft2 + Re(<.,Vo>) collapsed to a real [9][9][9] map
// ---------------------------------------------------------------------------
__device__ __forceinline__ float gridval(const float* __restrict__ Ur,
                                         const float* __restrict__ Ui,
                                         int a, int s, int t,
                                         const float* C, const float* S) {
    float acc = 0.0f;
    #pragma unroll
    for (int v = 0; v < 5; v++) {
        float gr = 0.0f, gi = 0.0f;
        int jj = (v + 4) % 9 - 2;                 // padded col -> U col
        if (jj >= 0 && jj < 5) {
            #pragma unroll
            for (int u = 0; u < 9; u++) {
                int ii = (u + 4) % 9 - 2;         // padded row -> U row
                if (ii >= 0 && ii < 5) {
                    float cr = Ur[a * 25 + ii * 5 + jj];
                    float ci = Ui[a * 25 + ii * 5 + jj];
                    int k = (u * s) % 9;
                    gr += cr * C[k] - ci * S[k];
                    gi += cr * S[k] + ci * C[k];
                }
            }
        }
        if (v == 0) {
            acc += gr;                             // Im(DC) dropped (numpy irfft)
        } else {
            int k2 = (v * t) % 9;
            acc += 2.0f * (gr * C[k2] - gi * S[k2]);
        }
    }
    return acc * (1.0f / 81.0f);
}

__global__ void kprep(const float* __restrict__ Uxr, const float* __restrict__ Uxi,
                      const float* __restrict__ Ufr, const float* __restrict__ Ufi,
                      const float* __restrict__ Vr,  const float* __restrict__ Vi,
                      const float* __restrict__ denom) {
    __shared__ float C9[9], S9[9];
    __shared__ float Gx[729], Gf[729], Pm[729];
    int tid = threadIdx.x;

    if (tid < 9) {
        double ang = 2.0 * 3.14159265358979323846 * (double)tid / 9.0;
        C9[tid] = (float)cos(ang);
        S9[tid] = (float)sin(ang);
    }
    __syncthreads();

    if (tid < 729) {
        {   // grid bases: tid = a*81 + s*9 + t
            int a = tid / 81, s = (tid / 9) % 9, t = tid % 9;
            Gx[tid] = gridval(Uxr, Uxi, a, s, t, C9, S9);
            Gf[tid] = gridval(Ufr, Ufi, a, s, t, C9, S9);
        }
        {   // projection: tid = (s*9+t)*9 + d
            int st = tid / 9, d = tid % 9;
            int s = st / 9, t = st % 9;
            float p = 0.0f;
            #pragma unroll
            for (int u = 0; u < 9; u++) {
                #pragma unroll
                for (int k = 0; k < 5; k++) {
                    int th = (u * s + k * t) % 9;
                    p += Vr[u * 45 + k * 9 + d] * C9[th]
                       + Vi[u * 45 + k * 9 + d] * S9[th];
                }
            }
            Pm[tid] = p;
        }
    }
    __syncthreads();

    float inv = 1.0f / denom[0];
    if (tid < 729) {
        int a = tid / 81, b = (tid / 9) % 9, d = tid % 9;
        float acc = 0.0f;
        #pragma unroll 9
        for (int st = 0; st < 81; st++)
            acc += Gx[a * 81 + st] * Gf[b * 81 + st] * Pm[st * 9 + d];
        g_T[(a * 9 + b) * 12 + d] = acc * inv;
    }
    if (tid < 243) {  // zero the pad lanes d = 9..11
        int ab = tid / 3;
        g_T[ab * 12 + 9 + tid % 3] = 0.0f;
    }
}

// ---------------------------------------------------------------------------
// kzero: clear output (harness poisons it with 0xAA)
// ---------------------------------------------------------------------------
__global__ void kzero(float* __restrict__ o, int n) {
    int i = blockIdx.x * 256 + threadIdx.x;
    if (i < n) o[i] = 0.0f;
}

// ---------------------------------------------------------------------------
// kmlp: per-edge 3-layer MLP  (8 -> 64 -> 64 -> 48), writes g_w[e][48]
//   weights staged in shared; h2 is folded directly into layer-3 accumulators
//   so peak live registers ~ h1[64] + acc3[48].
// ---------------------------------------------------------------------------
__global__ void __launch_bounds__(128) kmlp(const float* __restrict__ win,
                                            const float* __restrict__ W1,
                                            const float* __restrict__ W2,
                                            const float* __restrict__ W3,
                                            int E) {
    __shared__ float4 w1s[128];   // 8x64
    __shared__ float4 w2s[1024];  // 64x64
    __shared__ float4 w3s[768];   // 64x48
    int tid = threadIdx.x;

    const float4* W1v = (const float4*)W1;
    const float4* W2v = (const float4*)W2;
    const float4* W3v = (const float4*)W3;
    w1s[tid] = W1v[tid];
    #pragma unroll
    for (int i = 0; i < 8; i++) w2s[tid + i * 128] = W2v[tid + i * 128];
    #pragma unroll
    for (int i = 0; i < 6; i++) w3s[tid + i * 128] = W3v[tid + i * 128];
    __syncthreads();

    int e = blockIdx.x * 128 + tid;
    if (e >= E) return;

    float4 wa = ((const float4*)win)[e * 2 + 0];
    float4 wb = ((const float4*)win)[e * 2 + 1];
    float wi[8] = {wa.x, wa.y, wa.z, wa.w, wb.x, wb.y, wb.z, wb.w};

    // ----- layer 1: h1 = ssp(win @ W1 / sqrt(8)) -----
    const float s1 = 0.35355339059327373f;
    float h1[64];
    #pragma unroll
    for (int kk = 0; kk < 16; kk++) {
        float ax = 0.f, ay = 0.f, az = 0.f, aw4 = 0.f;
        #pragma unroll
        for (int i = 0; i < 8; i++) {
            float4 wv = w1s[i * 16 + kk];
            float v = wi[i];
            ax += v * wv.x; ay += v * wv.y; az += v * wv.z; aw4 += v * wv.w;
        }
        h1[kk * 4 + 0] = sspf(ax * s1);
        h1[kk * 4 + 1] = sspf(ay * s1);
        h1[kk * 4 + 2] = sspf(az * s1);
        h1[kk * 4 + 3] = sspf(aw4 * s1);
    }

    // ----- layers 2+3 fused: h2_k = ssp((h1@W2)*0.125); acc3 += h2_k * W3[k] -----
    float a3x[12], a3y[12], a3z[12], a3w[12];
    #pragma unroll
    for (int q = 0; q < 12; q++) { a3x[q] = 0.f; a3y[q] = 0.f; a3z[q] = 0.f; a3w[q] = 0.f; }

    #pragma unroll 1
    for (int kk = 0; kk < 16; kk++) {
        float ax = 0.f, ay = 0.f, az = 0.f, aw4 = 0.f;
        #pragma unroll
        for (int j = 0; j < 64; j++) {
            float4 wv = w2s[j * 16 + kk];
            float v = h1[j];
            ax += v * wv.x; ay += v * wv.y; az += v * wv.z; aw4 += v * wv.w;
        }
        float h2v[4];
        h2v[0] = sspf(ax * 0.125f);
        h2v[1] = sspf(ay * 0.125f);
        h2v[2] = sspf(az * 0.125f);
        h2v[3] = sspf(aw4 * 0.125f);
        #pragma unroll
        for (int c = 0; c < 4; c++) {
            int j3 = kk * 4 + c;
            float hv = h2v[c];
            #pragma unroll
            for (int q = 0; q < 12; q++) {
                float4 wv = w3s[j3 * 12 + q];
                a3x[q] += hv * wv.x; a3y[q] += hv * wv.y;
                a3z[q] += hv * wv.z; a3w[q] += hv * wv.w;
            }
        }
    }

    float4* gwv = (float4*)&g_w[(size_t)e * 48];
    #pragma unroll
    for (int q = 0; q < 12; q++) {
        float4 v;
        v.x = a3x[q] * 0.125f; v.y = a3y[q] * 0.125f;
        v.z = a3z[q] * 0.125f; v.w = a3w[q] * 0.125f;
        gwv[q] = v;
    }
}

// ---------------------------------------------------------------------------
// kmsg: per-edge message + scatter
//   S[a][d] = sum_b fs[b] T[a,b,d]      (729 FMA, T from smem, float4 rows)
//   msg[m][d] = sum_a x[src,m,a] S[a,d]; factor = (w[m] @ a_w)[d]
//   out[dst,m,d] += msg*factor  (scalar atomicAdd)
// ---------------------------------------------------------------------------
__global__ void __launch_bounds__(128) kmsg(const float* __restrict__ x,
                                            const float* __restrict__ fsph,
                                            const int*   __restrict__ eidx,
                                            const float* __restrict__ aw,
                                            float* __restrict__ out,
                                            int E) {
    __shared__ __align__(16) float Tsh[972];
    __shared__ float awsh[27];
    int tid = threadIdx.x;
    #pragma unroll
    for (int i = 0; i < 8; i++) {
        int idx = tid + i * 128;
        if (idx < 972) Tsh[idx] = g_T[idx];
    }
    if (tid < 27) awsh[tid] = aw[tid];
    __syncthreads();

    int e = blockIdx.x * 128 + tid;
    if (e >= E) return;

    int dst = eidx[e];
    int src = eidx[E + e];

    float f9[9];
    #pragma unroll
    for (int b = 0; b < 9; b++) f9[b] = __ldg(&fsph[e * 9 + b]);

    float Sv[81];
    #pragma unroll
    for (int a = 0; a < 9; a++) {
        float s0x = 0.f, s0y = 0.f, s0z = 0.f, s0w = 0.f;
        float s1x = 0.f, s1y = 0.f, s1z = 0.f, s1w = 0.f;
        float s2 = 0.f;
        #pragma unroll
        for (int b = 0; b < 9; b++) {
            float fb = f9[b];
            const float4* tp = (const float4*)&Tsh[(a * 9 + b) * 12];
            float4 t0 = tp[0];
            float4 t1 = tp[1];
            float  t2 = Tsh[(a * 9 + b) * 12 + 8];
            s0x += fb * t0.x; s0y += fb * t0.y; s0z += fb * t0.z; s0w += fb * t0.w;
            s1x += fb * t1.x; s1y += fb * t1.y; s1z += fb * t1.z; s1w += fb * t1.w;
            s2  += fb * t2;
        }
        Sv[a * 9 + 0] = s0x; Sv[a * 9 + 1] = s0y; Sv[a * 9 + 2] = s0z; Sv[a * 9 + 3] = s0w;
        Sv[a * 9 + 4] = s1x; Sv[a * 9 + 5] = s1y; Sv[a * 9 + 6] = s1z; Sv[a * 9 + 7] = s1w;
        Sv[a * 9 + 8] = s2;
    }

    const float* xb = x + (size_t)src * 144;
    const float* wb = g_w + (size_t)e * 48;
    float* ob = out + (size_t)dst * 144;

    #pragma unroll 2
    for (int m = 0; m < 16; m++) {
        float xv[9];
        #pragma unroll
        for (int a = 0; a < 9; a++) xv[a] = __ldg(&xb[m * 9 + a]);
        float w0 = __ldg(&wb[m * 3 + 0]);
        float w1 = __ldg(&wb[m * 3 + 1]);
        float w2 = __ldg(&wb[m * 3 + 2]);
        #pragma unroll
        for (int d = 0; d < 9; d++) {
            float msg = 0.f;
            #pragma unroll
            for (int a = 0; a < 9; a++) msg += xv[a] * Sv[a * 9 + d];
            float fac = w0 * awsh[d] + w1 * awsh[9 + d] + w2 * awsh[18 + d];
            atomicAdd(&ob[m * 9 + d], msg * fac);
        }
    }
}

// ---------------------------------------------------------------------------
// kernel_launch
// inputs: 0:x 1:filter_sph 2:weight_in 3:edge_idx 4:Ux_re 5:Ux_im 6:Uf_re
//         7:Uf_im 8:Vout_re 9:Vout_im 10:W1 11:W2 12:W3 13:a_w 14:denominator
// ---------------------------------------------------------------------------
extern "C" void kernel_launch(void* const* d_in, const int* in_sizes, int n_in,
                              void* d_out, int out_size) {
    const float* x    = (const float*)d_in[0];
    const float* fsph = (const float*)d_in[1];
    const float* win  = (const float*)d_in[2];
    const int*   eidx = (const int*)  d_in[3];
    const float* Uxr  = (const float*)d_in[4];
    const float* Uxi  = (const float*)d_in[5];
    const float* Ufr  = (const float*)d_in[6];
    const float* Ufi  = (const float*)d_in[7];
    const float* Vr   = (const float*)d_in[8];
    const float* Vi   = (const float*)d_in[9];
    const float* W1   = (const float*)d_in[10];
    const float* W2   = (const float*)d_in[11];
    const float* W3   = (const float*)d_in[12];
    const float* aw   = (const float*)d_in[13];
    const float* den  = (const float*)d_in[14];
    float* out = (float*)d_out;

    int E = in_sizes[1] / 9;   // filter_sph is [E, 9]

    kprep<<<1, 729>>>(Uxr, Uxi, Ufr, Ufi, Vr, Vi, den);
    kzero<<<(out_size + 255) / 256, 256>>>(out, out_size);
    kmlp<<<(E + 127) / 128, 128>>>(win, W1, W2, W3, E);
    kmsg<<<(E + 127) / 128, 128>>>(x, fsph, eidx, aw, out, E);
}

// round 3
// speedup vs baseline: 1.7882x; 1.7882x over previous
#include <cuda_runtime.h>

// Problem constants (fixed shapes for this problem)
#define NNODE 10000
#define NEDGE 160000
#define NMUL  16

// Scratch (static device arrays — cudaMalloc is forbidden)
__device__ __align__(16) float g_T[972];                 // T[a][b][d] padded to [81][12]
__device__ __align__(16) float g_w[(size_t)NEDGE * 48];  // MLP output w[e][48]

typedef unsigned long long u64;

// ---------------------------------------------------------------------------
// packed f32x2 helpers (Blackwell FFMA2)
// ---------------------------------------------------------------------------
__device__ __forceinline__ u64 pk2(float x, float y) {
    u64 r; asm("mov.b64 %0, {%1, %2};" : "=l"(r) : "f"(x), "f"(y)); return r;
}
__device__ __forceinline__ void up2(u64 v, float& x, float& y) {
    asm("mov.b64 {%0, %1}, %2;" : "=f"(x), "=f"(y) : "l"(v));
}
__device__ __forceinline__ u64 ffma2(u64 a, u64 b, u64 c) {
    u64 d; asm("fma.rn.f32x2 %0, %1, %2, %3;" : "=l"(d) : "l"(a), "l"(b), "l"(c));
    return d;
}

// ---------------------------------------------------------------------------
// ShiftedSoftPlus: softplus(x) - ln2, stable form max(x,0)+log1p(exp(-|x|))
// ---------------------------------------------------------------------------
__device__ __forceinline__ float sspf(float x) {
    float e = __expf(-fabsf(x));
    return fmaxf(x, 0.0f) + __logf(1.0f + e) - 0.69314718055994531f;
}

// ---------------------------------------------------------------------------
// kprep: build T[a][b][d] = sum_{s,t} Gx[a,s,t] * Gf[b,s,t] * P[s,t,d] / denom
// ---------------------------------------------------------------------------
__device__ __forceinline__ float gridval(const float* __restrict__ Ur,
                                         const float* __restrict__ Ui,
                                         int a, int s, int t,
                                         const float* C, const float* S) {
    float acc = 0.0f;
    #pragma unroll
    for (int v = 0; v < 5; v++) {
        float gr = 0.0f, gi = 0.0f;
        int jj = (v + 4) % 9 - 2;                 // padded col -> U col
        if (jj >= 0 && jj < 5) {
            #pragma unroll
            for (int u = 0; u < 9; u++) {
                int ii = (u + 4) % 9 - 2;         // padded row -> U row
                if (ii >= 0 && ii < 5) {
                    float cr = Ur[a * 25 + ii * 5 + jj];
                    float ci = Ui[a * 25 + ii * 5 + jj];
                    int k = (u * s) % 9;
                    gr += cr * C[k] - ci * S[k];
                    gi += cr * S[k] + ci * C[k];
                }
            }
        }
        if (v == 0) {
            acc += gr;                             // Im(DC) dropped (numpy irfft)
        } else {
            int k2 = (v * t) % 9;
            acc += 2.0f * (gr * C[k2] - gi * S[k2]);
        }
    }
    return acc * (1.0f / 81.0f);
}

__global__ void kprep(const float* __restrict__ Uxr, const float* __restrict__ Uxi,
                      const float* __restrict__ Ufr, const float* __restrict__ Ufi,
                      const float* __restrict__ Vr,  const float* __restrict__ Vi,
                      const float* __restrict__ denom) {
    __shared__ float C9[9], S9[9];
    __shared__ float Gx[729], Gf[729], Pm[729];
    int tid = threadIdx.x;

    if (tid < 9) {
        double ang = 2.0 * 3.14159265358979323846 * (double)tid / 9.0;
        C9[tid] = (float)cos(ang);
        S9[tid] = (float)sin(ang);
    }
    __syncthreads();

    if (tid < 729) {
        {   // grid bases: tid = a*81 + s*9 + t
            int a = tid / 81, s = (tid / 9) % 9, t = tid % 9;
            Gx[tid] = gridval(Uxr, Uxi, a, s, t, C9, S9);
            Gf[tid] = gridval(Ufr, Ufi, a, s, t, C9, S9);
        }
        {   // projection: tid = (s*9+t)*9 + d
            int st = tid / 9, d = tid % 9;
            int s = st / 9, t = st % 9;
            float p = 0.0f;
            #pragma unroll
            for (int u = 0; u < 9; u++) {
                #pragma unroll
                for (int k = 0; k < 5; k++) {
                    int th = (u * s + k * t) % 9;
                    p += Vr[u * 45 + k * 9 + d] * C9[th]
                       + Vi[u * 45 + k * 9 + d] * S9[th];
                }
            }
            Pm[tid] = p;
        }
    }
    __syncthreads();

    float inv = 1.0f / denom[0];
    if (tid < 729) {
        int a = tid / 81, b = (tid / 9) % 9, d = tid % 9;
        float acc = 0.0f;
        #pragma unroll 9
        for (int st = 0; st < 81; st++)
            acc += Gx[a * 81 + st] * Gf[b * 81 + st] * Pm[st * 9 + d];
        g_T[(a * 9 + b) * 12 + d] = acc * inv;
    }
    if (tid < 243) {  // zero the pad lanes d = 9..11
        int ab = tid / 3;
        g_T[ab * 12 + 9 + tid % 3] = 0.0f;
    }
}

// ---------------------------------------------------------------------------
// kzero: clear output (harness poisons it with 0xAA)
// ---------------------------------------------------------------------------
__global__ void kzero(float* __restrict__ o, int n) {
    int i = blockIdx.x * 256 + threadIdx.x;
    if (i < n) o[i] = 0.0f;
}

// ---------------------------------------------------------------------------
// kmlp: per-edge 3-layer MLP (8 -> 64 -> 64 -> 48), layers 2+3 in packed
// FFMA2 (fma.rn.f32x2): smem float4 weight rows give output pairs, the
// activation scalar is broadcast-packed via mov.b64 (ALU pipe, idle).
// ---------------------------------------------------------------------------
__global__ void __launch_bounds__(128) kmlp(const float* __restrict__ win,
                                            const float* __restrict__ W1,
                                            const float* __restrict__ W2,
                                            const float* __restrict__ W3,
                                            int E) {
    __shared__ float4 w1s[128];   // 8x64
    __shared__ float4 w2s[1024];  // 64x64
    __shared__ float4 w3s[768];   // 64x48
    int tid = threadIdx.x;

    const float4* W1v = (const float4*)W1;
    const float4* W2v = (const float4*)W2;
    const float4* W3v = (const float4*)W3;
    w1s[tid] = W1v[tid];
    #pragma unroll
    for (int i = 0; i < 8; i++) w2s[tid + i * 128] = W2v[tid + i * 128];
    #pragma unroll
    for (int i = 0; i < 6; i++) w3s[tid + i * 128] = W3v[tid + i * 128];
    __syncthreads();

    int e = blockIdx.x * 128 + tid;
    if (e >= E) return;

    float4 wa = ((const float4*)win)[e * 2 + 0];
    float4 wb = ((const float4*)win)[e * 2 + 1];
    float wi[8] = {wa.x, wa.y, wa.z, wa.w, wb.x, wb.y, wb.z, wb.w};

    // ----- layer 1: h1 = ssp(win @ W1 / sqrt(8)) -----
    const float s1 = 0.35355339059327373f;
    float h1[64];
    #pragma unroll
    for (int kk = 0; kk < 16; kk++) {
        float ax = 0.f, ay = 0.f, az = 0.f, aw4 = 0.f;
        #pragma unroll
        for (int i = 0; i < 8; i++) {
            float4 wv = w1s[i * 16 + kk];
            float v = wi[i];
            ax += v * wv.x; ay += v * wv.y; az += v * wv.z; aw4 += v * wv.w;
        }
        h1[kk * 4 + 0] = sspf(ax * s1);
        h1[kk * 4 + 1] = sspf(ay * s1);
        h1[kk * 4 + 2] = sspf(az * s1);
        h1[kk * 4 + 3] = sspf(aw4 * s1);
    }

    // ----- layers 2+3 fused, packed f32x2 -----
    const ulonglong2* w2p = (const ulonglong2*)w2s;
    const ulonglong2* w3p = (const ulonglong2*)w3s;

    u64 acc3[24];
    #pragma unroll
    for (int q = 0; q < 24; q++) acc3[q] = 0ull;

    #pragma unroll 1
    for (int kk = 0; kk < 16; kk++) {
        u64 a0 = 0ull, a1 = 0ull;     // outputs kk*4 + {0,1} and {2,3}
        #pragma unroll
        for (int j = 0; j < 64; j++) {
            u64 hj = pk2(h1[j], h1[j]);
            ulonglong2 wp = w2p[j * 16 + kk];
            a0 = ffma2(hj, wp.x, a0);
            a1 = ffma2(hj, wp.y, a1);
        }
        float v0, v1, v2, v3;
        up2(a0, v0, v1); up2(a1, v2, v3);
        float h2v[4];
        h2v[0] = sspf(v0 * 0.125f);
        h2v[1] = sspf(v1 * 0.125f);
        h2v[2] = sspf(v2 * 0.125f);
        h2v[3] = sspf(v3 * 0.125f);
        #pragma unroll
        for (int c = 0; c < 4; c++) {
            int j3 = kk * 4 + c;
            u64 hv = pk2(h2v[c], h2v[c]);
            #pragma unroll
            for (int q = 0; q < 12; q++) {
                ulonglong2 wp = w3p[j3 * 12 + q];
                acc3[2 * q + 0] = ffma2(hv, wp.x, acc3[2 * q + 0]);
                acc3[2 * q + 1] = ffma2(hv, wp.y, acc3[2 * q + 1]);
            }
        }
    }

    float4* gwv = (float4*)&g_w[(size_t)e * 48];
    #pragma unroll
    for (int q = 0; q < 12; q++) {
        float p0, p1, p2, p3;
        up2(acc3[2 * q + 0], p0, p1);
        up2(acc3[2 * q + 1], p2, p3);
        gwv[q] = make_float4(p0 * 0.125f, p1 * 0.125f, p2 * 0.125f, p3 * 0.125f);
    }
}

// ---------------------------------------------------------------------------
// kmsg: per-edge message + scatter
//   S[a][d] = sum_b fs[b] T[a,b,d]          (smem T, float4 rows)
//   per 4-mul chunk: gather x as 9 float4, w as 3 float4, compute each output
//   float4 on the fly, scatter with red.global.add.v4.f32 (36 vec-atomics/edge
//   instead of 144 scalar).
// ---------------------------------------------------------------------------
__global__ void __launch_bounds__(128, 3) kmsg(const float* __restrict__ x,
                                               const float* __restrict__ fsph,
                                               const int*   __restrict__ eidx,
                                               const float* __restrict__ aw,
                                               float* __restrict__ out,
                                               int E) {
    __shared__ __align__(16) float Tsh[972];
    __shared__ float awsh[27];
    int tid = threadIdx.x;
    #pragma unroll
    for (int i = 0; i < 8; i++) {
        int idx = tid + i * 128;
        if (idx < 972) Tsh[idx] = g_T[idx];
    }
    if (tid < 27) awsh[tid] = aw[tid];
    __syncthreads();

    int e = blockIdx.x * 128 + tid;
    if (e >= E) return;

    int dst = __ldg(&eidx[e]);
    int src = __ldg(&eidx[E + e]);

    float f9[9];
    #pragma unroll
    for (int b = 0; b < 9; b++) f9[b] = __ldg(&fsph[e * 9 + b]);

    float Sv[81];
    #pragma unroll
    for (int a = 0; a < 9; a++) {
        float s0x = 0.f, s0y = 0.f, s0z = 0.f, s0w = 0.f;
        float s1x = 0.f, s1y = 0.f, s1z = 0.f, s1w = 0.f;
        float s2 = 0.f;
        #pragma unroll
        for (int b = 0; b < 9; b++) {
            float fb = f9[b];
            const float4* tp = (const float4*)&Tsh[(a * 9 + b) * 12];
            float4 t0 = tp[0];
            float4 t1 = tp[1];
            float  t2 = Tsh[(a * 9 + b) * 12 + 8];
            s0x += fb * t0.x; s0y += fb * t0.y; s0z += fb * t0.z; s0w += fb * t0.w;
            s1x += fb * t1.x; s1y += fb * t1.y; s1z += fb * t1.z; s1w += fb * t1.w;
            s2  += fb * t2;
        }
        Sv[a * 9 + 0] = s0x; Sv[a * 9 + 1] = s0y; Sv[a * 9 + 2] = s0z; Sv[a * 9 + 3] = s0w;
        Sv[a * 9 + 4] = s1x; Sv[a * 9 + 5] = s1y; Sv[a * 9 + 6] = s1z; Sv[a * 9 + 7] = s1w;
        Sv[a * 9 + 8] = s2;
    }

    const float4* xq4 = (const float4*)(x + (size_t)src * 144);
    const float4* wq4 = (const float4*)(g_w + (size_t)e * 48);
    float* ob = out + (size_t)dst * 144;

    // 4 chunks of 4 muls; each chunk = 36 floats = 9 aligned float4 outputs
    #pragma unroll 1
    for (int c = 0; c < 4; c++) {
        float xf[36];
        #pragma unroll
        for (int q = 0; q < 9; q++) {
            float4 v = __ldg(&xq4[c * 9 + q]);
            xf[q * 4 + 0] = v.x; xf[q * 4 + 1] = v.y;
            xf[q * 4 + 2] = v.z; xf[q * 4 + 3] = v.w;
        }
        float wf[12];
        #pragma unroll
        for (int q = 0; q < 3; q++) {
            float4 v = __ldg(&wq4[c * 3 + q]);
            wf[q * 4 + 0] = v.x; wf[q * 4 + 1] = v.y;
            wf[q * 4 + 2] = v.z; wf[q * 4 + 3] = v.w;
        }

        #pragma unroll
        for (int q = 0; q < 9; q++) {
            float r[4];
            #pragma unroll
            for (int i = 0; i < 4; i++) {
                const int cf = q * 4 + i;      // flat index within chunk
                const int mm = cf / 9;         // mul within chunk (0..3)
                const int d  = cf % 9;
                float s = 0.f;
                #pragma unroll
                for (int a = 0; a < 9; a++) s += xf[mm * 9 + a] * Sv[a * 9 + d];
                float fac = wf[mm * 3 + 0] * awsh[d]
                          + wf[mm * 3 + 1] * awsh[9 + d]
                          + wf[mm * 3 + 2] * awsh[18 + d];
                r[i] = s * fac;
            }
            asm volatile("red.global.add.v4.f32 [%0], {%1, %2, %3, %4};"
                         :: "l"(ob + c * 36 + q * 4),
                            "f"(r[0]), "f"(r[1]), "f"(r[2]), "f"(r[3])
                         : "memory");
        }
    }
}

// ---------------------------------------------------------------------------
// kernel_launch
// inputs: 0:x 1:filter_sph 2:weight_in 3:edge_idx 4:Ux_re 5:Ux_im 6:Uf_re
//         7:Uf_im 8:Vout_re 9:Vout_im 10:W1 11:W2 12:W3 13:a_w 14:denominator
// ---------------------------------------------------------------------------
extern "C" void kernel_launch(void* const* d_in, const int* in_sizes, int n_in,
                              void* d_out, int out_size) {
    const float* x    = (const float*)d_in[0];
    const float* fsph = (const float*)d_in[1];
    const float* win  = (const float*)d_in[2];
    const int*   eidx = (const int*)  d_in[3];
    const float* Uxr  = (const float*)d_in[4];
    const float* Uxi  = (const float*)d_in[5];
    const float* Ufr  = (const float*)d_in[6];
    const float* Ufi  = (const float*)d_in[7];
    const float* Vr   = (const float*)d_in[8];
    const float* Vi   = (const float*)d_in[9];
    const float* W1   = (const float*)d_in[10];
    const float* W2   = (const float*)d_in[11];
    const float* W3   = (const float*)d_in[12];
    const float* aw   = (const float*)d_in[13];
    const float* den  = (const float*)d_in[14];
    float* out = (float*)d_out;

    int E = in_sizes[1] / 9;   // filter_sph is [E, 9]

    kprep<<<1, 729>>>(Uxr, Uxi, Ufr, Ufi, Vr, Vi, den);
    kzero<<<(out_size + 255) / 256, 256>>>(out, out_size);
    kmlp<<<(E + 127) / 128, 128>>>(win, W1, W2, W3, E);
    kmsg<<<(E + 127) / 128, 128>>>(x, fsph, eidx, aw, out, E);
}